// round 3
// baseline (speedup 1.0000x reference)
#include <cuda_runtime.h>
#include <cstdint>
#include <cstddef>

// Problem constants
#define BATCH   1024
#define SEQ     512
#define NFEAT   64
#define HID     128
#define GATES   512          // 4*HID
#define NOUT    128

// LSTM persistent kernel config
#define NCTA    128
#define BR      8            // batch rows per CTA (1024/128)
#define LTHREADS 512

// Scratch (device globals; no allocations allowed)
__device__ float  g_xg[(size_t)BATCH * SEQ * GATES];   // 1 GiB: precomputed x@W_ih^T + b_ih + b_hh, layout [bt][gate]
__device__ float4 g_Wq[32 * GATES];                    // repacked W_hh: [k4][n] -> float4 of W_hh[n][4k4..4k4+3]

// ---------------------------------------------------------------------------
// f32x2 packed FMA helper: acc(2xf32 in b64) += a * b, elementwise
// ---------------------------------------------------------------------------
__device__ __forceinline__ void ffma2(unsigned long long& d,
                                      unsigned long long a,
                                      unsigned long long b) {
    asm("fma.rn.f32x2 %0, %1, %2, %0;" : "+l"(d) : "l"(a), "l"(b));
}

__device__ __forceinline__ float hsum2(unsigned long long v) {
    float lo = __int_as_float((unsigned int)(v & 0xffffffffULL));
    float hi = __int_as_float((unsigned int)(v >> 32));
    return lo + hi;
}

__device__ __forceinline__ float sigmoidf_(float x) {
    return 1.0f / (1.0f + __expf(-x));
}

// ---------------------------------------------------------------------------
// Kernel 0: repack W_hh [512][128] row-major -> g_Wq[k4][n] (float4 along k)
// ---------------------------------------------------------------------------
__global__ void pack_whh_kernel(const float* __restrict__ Whh) {
    int n = threadIdx.x;   // 0..511
    const float4* row = (const float4*)(Whh + (size_t)n * HID);
#pragma unroll
    for (int k4 = 0; k4 < 32; k4++) {
        g_Wq[k4 * GATES + n] = row[k4];
    }
}

// ---------------------------------------------------------------------------
// Kernel 1: xg[bt][n] = sum_f x[bt][f] * W_ih[n][f] + b_ih[n] + b_hh[n]
// M = BATCH*SEQ = 524288 rows, N = 512, K = 64. Tile 64x64, full K in smem.
// 256 threads: tx = tid&31 (n = tx + j*32, j<2), ty = tid>>5 (m = ty + i*8, i<8)
// ---------------------------------------------------------------------------
__global__ __launch_bounds__(256) void xg_kernel(const float* __restrict__ x,
                                                 const float* __restrict__ Wih,
                                                 const float* __restrict__ b_ih,
                                                 const float* __restrict__ b_hh) {
    __shared__ float As[64][66];
    __shared__ float Bs[64][66];

    const int bt0 = blockIdx.x * 64;
    const int n0  = blockIdx.y * 64;
    const int tid = threadIdx.x;

    // Load tiles: both are fully contiguous 4096-float blocks (K == row width)
    const float4* Ag = (const float4*)(x   + (size_t)bt0 * NFEAT);
    const float4* Bg = (const float4*)(Wih + (size_t)n0  * NFEAT);
#pragma unroll
    for (int p = 0; p < 4; p++) {
        int v = tid + p * 256;          // float4 index, 0..1023
        int m = v >> 4;                 // 16 float4 per 64-float row
        int k = (v & 15) * 4;
        float4 qa = Ag[v];
        As[m][k] = qa.x; As[m][k+1] = qa.y; As[m][k+2] = qa.z; As[m][k+3] = qa.w;
        float4 qb = Bg[v];
        Bs[m][k] = qb.x; Bs[m][k+1] = qb.y; Bs[m][k+2] = qb.z; Bs[m][k+3] = qb.w;
    }
    __syncthreads();

    const int tx = tid & 31;
    const int ty = tid >> 5;

    unsigned long long acc[8][2];
#pragma unroll
    for (int i = 0; i < 8; i++)
#pragma unroll
        for (int j = 0; j < 2; j++) acc[i][j] = 0ULL;

#pragma unroll
    for (int k2 = 0; k2 < 32; k2++) {
        unsigned long long a2[8], b2[2];
#pragma unroll
        for (int i = 0; i < 8; i++)
            a2[i] = *(const unsigned long long*)&As[ty + i * 8][k2 * 2];
#pragma unroll
        for (int j = 0; j < 2; j++)
            b2[j] = *(const unsigned long long*)&Bs[tx + j * 32][k2 * 2];
#pragma unroll
        for (int i = 0; i < 8; i++)
#pragma unroll
            for (int j = 0; j < 2; j++)
                ffma2(acc[i][j], a2[i], b2[j]);
    }

    float bias[2];
#pragma unroll
    for (int j = 0; j < 2; j++) {
        int n = n0 + tx + j * 32;
        bias[j] = __ldg(&b_ih[n]) + __ldg(&b_hh[n]);
    }

#pragma unroll
    for (int i = 0; i < 8; i++) {
        int m = bt0 + ty + i * 8;
#pragma unroll
        for (int j = 0; j < 2; j++) {
            int n = n0 + tx + j * 32;
            g_xg[(size_t)m * GATES + n] = hsum2(acc[i][j]) + bias[j];
        }
    }
}

// ---------------------------------------------------------------------------
// Kernel 2: persistent LSTM. Each CTA owns BR=8 batch rows, loops T=512 steps.
// Thread n in [0,512): gate pre-activation dot-products for all 8 rows.
//   - k4 0..15 weights cached in smem, k4 16..31 streamed from L2 each step.
// Thread (rp,j): nonlinearity + state update; c in registers, h in smem.
// Final output projection fused at the end.
// ---------------------------------------------------------------------------
extern __shared__ char smem_raw[];

__global__ __launch_bounds__(LTHREADS, 1) void lstm_kernel(
        const float* __restrict__ W_out,
        const float* __restrict__ b_out,
        float* __restrict__ out) {

    // smem carve: weights (131072B) | h (4096B) | gates (16384B)
    ulonglong2* w4s = (ulonglong2*)smem_raw;                   // [16][512]
    float* h_s = (float*)(smem_raw + 131072);                  // [8][128]
    float* gs  = (float*)(smem_raw + 131072 + 4096);           // [8][512]

    const int tid = threadIdx.x;
    const int b0  = blockIdx.x * BR;
    const int n   = tid;

    const ulonglong2* Wg = (const ulonglong2*)g_Wq;

    // Load cached weight half (k4 0..15) and zero h
#pragma unroll
    for (int p = 0; p < 16; p++) {
        int idx = tid + p * LTHREADS;      // covers 16*512
        w4s[idx] = Wg[idx];
    }
#pragma unroll
    for (int p = 0; p < 2; p++) h_s[tid + p * LTHREADS] = 0.0f;
    __syncthreads();

    const int j  = tid & 127;
    const int rp = tid >> 7;               // 0..3 ; handles rows rp and rp+4
    float cst[2] = {0.0f, 0.0f};

    for (int t = 0; t < SEQ; t++) {
        // ---- Gate GEMM phase: thread n computes gs[r][n] for 8 rows ----
        unsigned long long acc[BR];
#pragma unroll
        for (int r = 0; r < BR; r++) acc[r] = 0ULL;

        // smem-cached half: k4 0..15
#pragma unroll
        for (int k4 = 0; k4 < 16; k4++) {
            ulonglong2 w = w4s[k4 * GATES + n];
#pragma unroll
            for (int r = 0; r < BR; r++) {
                ulonglong2 hh = *(const ulonglong2*)&h_s[r * HID + k4 * 4];
                ffma2(acc[r], hh.x, w.x);
                ffma2(acc[r], hh.y, w.y);
            }
        }

        // L2-streamed half: k4 16..31, rolling depth-4 prefetch
        ulonglong2 wb[4];
#pragma unroll
        for (int u = 0; u < 4; u++) wb[u] = Wg[(16 + u) * GATES + n];
#pragma unroll
        for (int c = 0; c < 4; c++) {
            ulonglong2 wc[4];
#pragma unroll
            for (int u = 0; u < 4; u++) wc[u] = wb[u];
            if (c < 3) {
#pragma unroll
                for (int u = 0; u < 4; u++)
                    wb[u] = Wg[(20 + c * 4 + u) * GATES + n];
            }
#pragma unroll
            for (int u = 0; u < 4; u++) {
                int k4 = 16 + c * 4 + u;
#pragma unroll
                for (int r = 0; r < BR; r++) {
                    ulonglong2 hh = *(const ulonglong2*)&h_s[r * HID + k4 * 4];
                    ffma2(acc[r], hh.x, wc[u].x);
                    ffma2(acc[r], hh.y, wc[u].y);
                }
            }
        }

#pragma unroll
        for (int r = 0; r < BR; r++)
            gs[r * GATES + n] = hsum2(acc[r]);

        __syncthreads();

        // ---- Nonlinearity + state update phase ----
#pragma unroll
        for (int p = 0; p < 2; p++) {
            int r = rp + p * 4;
            size_t base = ((size_t)((b0 + r) * SEQ + t)) * GATES;
            float gi = gs[r * GATES + j]             + __ldg(&g_xg[base + j]);
            float gf = gs[r * GATES + 128 + j]       + __ldg(&g_xg[base + 128 + j]);
            float gg = gs[r * GATES + 256 + j]       + __ldg(&g_xg[base + 256 + j]);
            float go = gs[r * GATES + 384 + j]       + __ldg(&g_xg[base + 384 + j]);
            float iv = sigmoidf_(gi);
            float fv = sigmoidf_(gf);
            float gv = tanhf(gg);
            float ov = sigmoidf_(go);
            float cc = fv * cst[p] + iv * gv;
            cst[p] = cc;
            h_s[r * HID + j] = ov * tanhf(cc);
        }
        __syncthreads();
    }

    // ---- Output projection: out[b][o] = h[b] . W_out[o] + b_out[o] ----
#pragma unroll
    for (int p = 0; p < 2; p++) {
        int idx = tid + p * LTHREADS;      // 0..1023 -> (r, o)
        int r = idx >> 7;
        int o = idx & 127;
        const float4* wo = (const float4*)(W_out + (size_t)o * HID);
        const float4* hr = (const float4*)&h_s[r * HID];
        float s = __ldg(&b_out[o]);
#pragma unroll
        for (int k4 = 0; k4 < 32; k4++) {
            float4 w = wo[k4];
            float4 h = hr[k4];
            s += w.x * h.x + w.y * h.y + w.z * h.z + w.w * h.w;
        }
        out[(size_t)(b0 + r) * NOUT + o] = s;
    }
}

// ---------------------------------------------------------------------------
// Launch
// ---------------------------------------------------------------------------
extern "C" void kernel_launch(void* const* d_in, const int* in_sizes, int n_in,
                              void* d_out, int out_size) {
    const float* x     = (const float*)d_in[0];
    const float* W_ih  = (const float*)d_in[1];
    const float* W_hh  = (const float*)d_in[2];
    const float* b_ih  = (const float*)d_in[3];
    const float* b_hh  = (const float*)d_in[4];
    const float* W_out = (const float*)d_in[5];
    const float* b_out = (const float*)d_in[6];
    float* out = (float*)d_out;

    // Persistent kernel needs 148 KB dynamic smem
    const int lstm_smem = 131072 + 4096 + 16384;
    cudaFuncSetAttribute(lstm_kernel,
                         cudaFuncAttributeMaxDynamicSharedMemorySize, lstm_smem);

    pack_whh_kernel<<<1, GATES>>>(W_hh);

    dim3 grid1((BATCH * SEQ) / 64, GATES / 64);
    xg_kernel<<<grid1, 256>>>(x, W_ih, b_ih, b_hh);

    lstm_kernel<<<NCTA, LTHREADS, lstm_smem>>>(W_out, b_out, out);
}